// round 2
// baseline (speedup 1.0000x reference)
#include <cuda_runtime.h>
#include <cstdint>

// EnvironmentalAugmentations: pink = IIR(white, a=0.99, b=0.01); mixed = wave + 0.05*pink;
// out = mixed / max(|mixed|) if max > 1 else mixed.
//
// Strategy:
//  - IIR parallelized per (channel, chunk) warp-tile with 1024-sample warm-up
//    (0.99^1024 ~ 3.4e-5 -> output error ~7e-7, far under 1e-3 threshold).
//  - Within a warp: float4 per lane, 4-elem local scan, 5-step shuffle scan
//    (first-order linear recurrence composition), 1-FMA carry chain per 128 elems.
//  - Pass 1 writes mixed to d_out and atomicMax's the global max.
//  - Pass 2 scales d_out in place.

#define A_COEF 0.99f
#define B_COEF 0.01f
#define NOISE_LEVEL 0.05f

__device__ int d_gmax;  // float bits of global max (all values >= 0 so int max == float max)

__global__ void reset_gmax_kernel() { d_gmax = 0; }

constexpr int WARPS_PB = 8;         // warps per block
constexpr int U_ELEMS  = 8192;      // useful elements per warp tile
constexpr int WARM     = 1024;      // warm-up elements (chunk > 0)
constexpr int GROUPS   = U_ELEMS / 128;
constexpr int WGROUPS  = WARM / 128;
constexpr int NCH      = 256;

__global__ __launch_bounds__(WARPS_PB * 32)
void pink_mix_kernel(const float* __restrict__ wave,
                     const float* __restrict__ wn,
                     float* __restrict__ out,
                     int T, int chunks)
{
    const int lane   = threadIdx.x & 31;
    const int warpId = threadIdx.x >> 5;
    const int wgid   = blockIdx.x * WARPS_PB + warpId;
    const int ch     = wgid / chunks;
    const int chunk  = wgid - ch * chunks;

    // Recurrence constants
    const float A1 = A_COEF;
    const float A2 = A1 * A1;
    const float A3 = A2 * A1;
    const float A4 = A2 * A2;
    const float A8 = A4 * A4;
    const float A16 = A8 * A8;
    const float A32 = A16 * A16;
    const float A64 = A32 * A32;
    const float A128 = A64 * A64;
    const float a4lane = powf(A4, (float)lane);   // a^(4*lane), once per thread

    float lmax = 0.0f;

    if (ch < NCH) {
        const long long row = (long long)ch * T;
        const float* __restrict__ wnr = wn   + row;
        const float* __restrict__ wvr = wave + row;
        float*       __restrict__ otr = out  + row;

        const int ustart = chunk * U_ELEMS;
        const int nWarm  = (chunk == 0) ? 0 : WGROUPS;
        int tg = (chunk == 0) ? 0 : (ustart - WARM);  // group base (warp-uniform)

        float Cc = 0.0f;  // carry = pink value at element (tg-1)

        // ---- warm-up groups: scan only, no output ----
        for (int g = 0; g < nWarm; ++g) {
            const int idx = tg + lane * 4;
            float4 w = *reinterpret_cast<const float4*>(wnr + idx);
            float g0 = B_COEF * w.x, g1 = B_COEF * w.y, g2 = B_COEF * w.z, g3 = B_COEF * w.w;
            float p1 = fmaf(A1, g0, g1);
            float p2 = fmaf(A1, p1, g2);
            float p3 = fmaf(A1, p2, g3);
            float tt = p3, u;
            u = __shfl_up_sync(0xffffffffu, tt, 1);  if (lane >= 1)  tt = fmaf(A4,  u, tt);
            u = __shfl_up_sync(0xffffffffu, tt, 2);  if (lane >= 2)  tt = fmaf(A8,  u, tt);
            u = __shfl_up_sync(0xffffffffu, tt, 4);  if (lane >= 4)  tt = fmaf(A16, u, tt);
            u = __shfl_up_sync(0xffffffffu, tt, 8);  if (lane >= 8)  tt = fmaf(A32, u, tt);
            u = __shfl_up_sync(0xffffffffu, tt, 16); if (lane >= 16) tt = fmaf(A64, u, tt);
            float T31 = __shfl_sync(0xffffffffu, tt, 31);
            Cc = fmaf(A128, Cc, T31);
            tg += 128;
        }

        // ---- useful groups: scan + mix + store + max ----
        for (int g = 0; g < GROUPS; ++g) {
            if (tg >= T) break;                      // warp-uniform
            const int idx = tg + lane * 4;
            const bool fullgrp = (tg + 128 <= T);

            float4 w;
            if (fullgrp) {
                w = *reinterpret_cast<const float4*>(wnr + idx);
            } else {
                w.x = (idx + 0 < T) ? wnr[idx + 0] : 0.0f;
                w.y = (idx + 1 < T) ? wnr[idx + 1] : 0.0f;
                w.z = (idx + 2 < T) ? wnr[idx + 2] : 0.0f;
                w.w = (idx + 3 < T) ? wnr[idx + 3] : 0.0f;
            }

            float g0 = B_COEF * w.x, g1 = B_COEF * w.y, g2 = B_COEF * w.z, g3 = B_COEF * w.w;
            if (idx == 0) g0 = w.x;                  // exact first element: pink[0] = w[0]
            float p0 = g0;
            float p1 = fmaf(A1, p0, g1);
            float p2 = fmaf(A1, p1, g2);
            float p3 = fmaf(A1, p2, g3);

            float tt = p3, u;
            u = __shfl_up_sync(0xffffffffu, tt, 1);  if (lane >= 1)  tt = fmaf(A4,  u, tt);
            u = __shfl_up_sync(0xffffffffu, tt, 2);  if (lane >= 2)  tt = fmaf(A8,  u, tt);
            u = __shfl_up_sync(0xffffffffu, tt, 4);  if (lane >= 4)  tt = fmaf(A16, u, tt);
            u = __shfl_up_sync(0xffffffffu, tt, 8);  if (lane >= 8)  tt = fmaf(A32, u, tt);
            u = __shfl_up_sync(0xffffffffu, tt, 16); if (lane >= 16) tt = fmaf(A64, u, tt);

            float Tm1 = __shfl_up_sync(0xffffffffu, tt, 1);
            float cin = fmaf(a4lane, Cc, (lane ? Tm1 : 0.0f));  // T_{lane-1} + a^{4*lane} * C

            float f0 = fmaf(A1, cin, p0);
            float f1 = fmaf(A2, cin, p1);
            float f2 = fmaf(A3, cin, p2);
            float f3 = fmaf(A4, cin, p3);

            float T31 = __shfl_sync(0xffffffffu, tt, 31);
            Cc = fmaf(A128, Cc, T31);

            if (fullgrp) {
                float4 v = *reinterpret_cast<const float4*>(wvr + idx);
                float4 o;
                o.x = fmaf(NOISE_LEVEL, f0, v.x);
                o.y = fmaf(NOISE_LEVEL, f1, v.y);
                o.z = fmaf(NOISE_LEVEL, f2, v.z);
                o.w = fmaf(NOISE_LEVEL, f3, v.w);
                *reinterpret_cast<float4*>(otr + idx) = o;
                lmax = fmaxf(lmax, fmaxf(fmaxf(fabsf(o.x), fabsf(o.y)),
                                         fmaxf(fabsf(o.z), fabsf(o.w))));
            } else {
                float fs[4] = {f0, f1, f2, f3};
                #pragma unroll
                for (int j = 0; j < 4; ++j) {
                    if (idx + j < T) {
                        float oo = fmaf(NOISE_LEVEL, fs[j], wvr[idx + j]);
                        otr[idx + j] = oo;
                        lmax = fmaxf(lmax, fabsf(oo));
                    }
                }
            }
            tg += 128;
        }
    }

    // ---- block max reduction + atomic ----
    #pragma unroll
    for (int o = 16; o; o >>= 1)
        lmax = fmaxf(lmax, __shfl_xor_sync(0xffffffffu, lmax, o));

    __shared__ float smax[WARPS_PB];
    if (lane == 0) smax[warpId] = lmax;
    __syncthreads();
    if (warpId == 0) {
        float m = (lane < WARPS_PB) ? smax[lane] : 0.0f;
        #pragma unroll
        for (int o = 4; o; o >>= 1)
            m = fmaxf(m, __shfl_xor_sync(0xffffffffu, m, o));
        if (lane == 0)
            atomicMax(&d_gmax, __float_as_int(m));  // values >= 0: int cmp == float cmp
    }
}

__global__ void scale_kernel(float* __restrict__ out, int n4)
{
    int i = blockIdx.x * blockDim.x + threadIdx.x;
    if (i >= n4) return;
    float mx = __int_as_float(d_gmax);
    float s = (mx > 1.0f) ? (1.0f / mx) : 1.0f;
    float4 v = reinterpret_cast<float4*>(out)[i];
    v.x *= s; v.y *= s; v.z *= s; v.w *= s;
    reinterpret_cast<float4*>(out)[i] = v;
}

extern "C" void kernel_launch(void* const* d_in, const int* in_sizes, int n_in,
                              void* d_out, int out_size)
{
    const float* wave = (const float*)d_in[0];
    const float* wn   = (const float*)d_in[1];
    float* out = (float*)d_out;

    const int total = in_sizes[0];
    const int T = total / NCH;                         // 220500
    const int chunks = (T + U_ELEMS - 1) / U_ELEMS;    // 27

    reset_gmax_kernel<<<1, 1>>>();

    // grid warps = 32*chunks*8 = 256*chunks == NCH*chunks exactly
    pink_mix_kernel<<<32 * chunks, WARPS_PB * 32>>>(wave, wn, out, T, chunks);

    const int n4 = total / 4;
    scale_kernel<<<(n4 + 255) / 256, 256>>>(out, n4);
}

// round 5
// speedup vs baseline: 1.1431x; 1.1431x over previous
#include <cuda_runtime.h>
#include <cuda_fp16.h>
#include <cstdint>

// EnvironmentalAugmentations: pink = IIR(white, a=0.99, b=0.01); mixed = wave + 0.05*pink;
// out = mixed / max(|mixed|) if max > 1 else mixed.
//
// R5 = third submission of the fp16-scratch design (R3/R4 hit broker-level container
// failures; R1 showed identical failures occur on kernels without static arrays and
// resolve on retry -> infra flake hypothesis, p~25% for two-in-a-row at observed rate).
//  - mixed stored as fp16 in __device__ scratch (halves pass1-store + pass2-read bytes).
//    fp16 rounding is relative (<=2^-11/elem) -> l2 rel_err ~3e-4 < 1e-3 gate.
//  - no reset kernel / no atomics: pass1 writes per-block maxima to a fixed array,
//    pass2 (grid-stride, 2048 blocks) reduces them and scales while expanding to fp32.
// Traffic: 1158MB -> 932MB; predicted ~168us (vs 211us fp32 baseline).

#define A_COEF 0.99f
#define B_COEF 0.01f
#define NOISE_LEVEL 0.05f

constexpr int WARPS_PB = 8;         // warps per block (pass 1)
constexpr int U_ELEMS  = 8192;      // useful elements per warp tile
constexpr int WARM     = 1024;      // warm-up elements (chunk > 0): 0.99^1024 ~ 3.4e-5
constexpr int GROUPS   = U_ELEMS / 128;
constexpr int WGROUPS  = WARM / 128;
constexpr int NCH      = 256;
constexpr int TOTAL_MAX = 56448000; // 256 * 220500

__device__ __half g_scratch[TOTAL_MAX];  // fp16 mixed
__device__ float  g_bmax[4096];          // per-block maxima (pass-1 grid <= 4096)

__global__ __launch_bounds__(WARPS_PB * 32)
void pink_mix_kernel(const float* __restrict__ wave,
                     const float* __restrict__ wn,
                     int T, int chunks)
{
    const int lane   = threadIdx.x & 31;
    const int warpId = threadIdx.x >> 5;
    const int wgid   = blockIdx.x * WARPS_PB + warpId;
    const int ch     = wgid / chunks;
    const int chunk  = wgid - ch * chunks;

    const float A1 = A_COEF;
    const float A2 = A1 * A1;
    const float A3 = A2 * A1;
    const float A4 = A2 * A2;
    const float A8 = A4 * A4;
    const float A16 = A8 * A8;
    const float A32 = A16 * A16;
    const float A64 = A32 * A32;
    const float A128 = A64 * A64;
    const float a4lane = powf(A4, (float)lane);   // a^(4*lane)

    float lmax = 0.0f;

    if (ch < NCH) {
        const long long row = (long long)ch * T;
        const float* __restrict__ wnr = wn   + row;
        const float* __restrict__ wvr = wave + row;
        __half*      __restrict__ scr = g_scratch + row;

        const int ustart = chunk * U_ELEMS;
        const int nWarm  = (chunk == 0) ? 0 : WGROUPS;
        int tg = (chunk == 0) ? 0 : (ustart - WARM);

        float Cc = 0.0f;  // carry = pink value at element (tg-1)

        // ---- warm-up groups: scan only ----
        for (int g = 0; g < nWarm; ++g) {
            const int idx = tg + lane * 4;
            float4 w = *reinterpret_cast<const float4*>(wnr + idx);
            float g0 = B_COEF * w.x, g1 = B_COEF * w.y, g2 = B_COEF * w.z, g3 = B_COEF * w.w;
            float p1 = fmaf(A1, g0, g1);
            float p2 = fmaf(A1, p1, g2);
            float p3 = fmaf(A1, p2, g3);
            float tt = p3, u;
            u = __shfl_up_sync(0xffffffffu, tt, 1);  if (lane >= 1)  tt = fmaf(A4,  u, tt);
            u = __shfl_up_sync(0xffffffffu, tt, 2);  if (lane >= 2)  tt = fmaf(A8,  u, tt);
            u = __shfl_up_sync(0xffffffffu, tt, 4);  if (lane >= 4)  tt = fmaf(A16, u, tt);
            u = __shfl_up_sync(0xffffffffu, tt, 8);  if (lane >= 8)  tt = fmaf(A32, u, tt);
            u = __shfl_up_sync(0xffffffffu, tt, 16); if (lane >= 16) tt = fmaf(A64, u, tt);
            float T31 = __shfl_sync(0xffffffffu, tt, 31);
            Cc = fmaf(A128, Cc, T31);
            tg += 128;
        }

        // ---- useful groups: scan + mix + fp16 store + max ----
        for (int g = 0; g < GROUPS; ++g) {
            if (tg >= T) break;                      // warp-uniform
            const int idx = tg + lane * 4;
            const bool fullgrp = (tg + 128 <= T);

            float4 w;
            if (fullgrp) {
                w = *reinterpret_cast<const float4*>(wnr + idx);
            } else {
                w.x = (idx + 0 < T) ? wnr[idx + 0] : 0.0f;
                w.y = (idx + 1 < T) ? wnr[idx + 1] : 0.0f;
                w.z = (idx + 2 < T) ? wnr[idx + 2] : 0.0f;
                w.w = (idx + 3 < T) ? wnr[idx + 3] : 0.0f;
            }

            float g0 = B_COEF * w.x, g1 = B_COEF * w.y, g2 = B_COEF * w.z, g3 = B_COEF * w.w;
            if (idx == 0) g0 = w.x;                  // exact: pink[0] = w[0]
            float p0 = g0;
            float p1 = fmaf(A1, p0, g1);
            float p2 = fmaf(A1, p1, g2);
            float p3 = fmaf(A1, p2, g3);

            float tt = p3, u;
            u = __shfl_up_sync(0xffffffffu, tt, 1);  if (lane >= 1)  tt = fmaf(A4,  u, tt);
            u = __shfl_up_sync(0xffffffffu, tt, 2);  if (lane >= 2)  tt = fmaf(A8,  u, tt);
            u = __shfl_up_sync(0xffffffffu, tt, 4);  if (lane >= 4)  tt = fmaf(A16, u, tt);
            u = __shfl_up_sync(0xffffffffu, tt, 8);  if (lane >= 8)  tt = fmaf(A32, u, tt);
            u = __shfl_up_sync(0xffffffffu, tt, 16); if (lane >= 16) tt = fmaf(A64, u, tt);

            float Tm1 = __shfl_up_sync(0xffffffffu, tt, 1);
            float cin = fmaf(a4lane, Cc, (lane ? Tm1 : 0.0f));

            float f0 = fmaf(A1, cin, p0);
            float f1 = fmaf(A2, cin, p1);
            float f2 = fmaf(A3, cin, p2);
            float f3 = fmaf(A4, cin, p3);

            float T31 = __shfl_sync(0xffffffffu, tt, 31);
            Cc = fmaf(A128, Cc, T31);

            if (fullgrp) {
                float4 v = *reinterpret_cast<const float4*>(wvr + idx);
                float o0 = fmaf(NOISE_LEVEL, f0, v.x);
                float o1 = fmaf(NOISE_LEVEL, f1, v.y);
                float o2 = fmaf(NOISE_LEVEL, f2, v.z);
                float o3 = fmaf(NOISE_LEVEL, f3, v.w);
                __half2 h01 = __floats2half2_rn(o0, o1);
                __half2 h23 = __floats2half2_rn(o2, o3);
                uint2 pk;
                pk.x = *reinterpret_cast<unsigned*>(&h01);
                pk.y = *reinterpret_cast<unsigned*>(&h23);
                *reinterpret_cast<uint2*>(scr + idx) = pk;   // 8B aligned: idx%4==0, row%4==0
                lmax = fmaxf(lmax, fmaxf(fmaxf(fabsf(o0), fabsf(o1)),
                                         fmaxf(fabsf(o2), fabsf(o3))));
            } else {
                float fs[4] = {f0, f1, f2, f3};
                #pragma unroll
                for (int j = 0; j < 4; ++j) {
                    if (idx + j < T) {
                        float oo = fmaf(NOISE_LEVEL, fs[j], wvr[idx + j]);
                        scr[idx + j] = __float2half_rn(oo);
                        lmax = fmaxf(lmax, fabsf(oo));
                    }
                }
            }
            tg += 128;
        }
    }

    // ---- block max reduction -> g_bmax[blockIdx.x] (no atomics, no reset) ----
    #pragma unroll
    for (int o = 16; o; o >>= 1)
        lmax = fmaxf(lmax, __shfl_xor_sync(0xffffffffu, lmax, o));

    __shared__ float smax[WARPS_PB];
    if (lane == 0) smax[warpId] = lmax;
    __syncthreads();
    if (warpId == 0) {
        float m = (lane < WARPS_PB) ? smax[lane] : 0.0f;
        #pragma unroll
        for (int o = 4; o; o >>= 1)
            m = fmaxf(m, __shfl_xor_sync(0xffffffffu, m, o));
        if (lane == 0) g_bmax[blockIdx.x] = m;
    }
}

// Pass 2: reduce per-block maxima, then expand fp16 scratch -> scaled fp32 out.
__global__ __launch_bounds__(256)
void scale_expand_kernel(float* __restrict__ out, int n4, int nb)
{
    // block-local reduction of g_bmax[0..nb)
    float m = 0.0f;
    for (int i = threadIdx.x; i < nb; i += 256)
        m = fmaxf(m, g_bmax[i]);
    #pragma unroll
    for (int o = 16; o; o >>= 1)
        m = fmaxf(m, __shfl_xor_sync(0xffffffffu, m, o));
    __shared__ float smax[8];
    if ((threadIdx.x & 31) == 0) smax[threadIdx.x >> 5] = m;
    __syncthreads();
    __shared__ float s_scale;
    if (threadIdx.x == 0) {
        float mm = smax[0];
        #pragma unroll
        for (int i = 1; i < 8; ++i) mm = fmaxf(mm, smax[i]);
        s_scale = (mm > 1.0f) ? (1.0f / mm) : 1.0f;
    }
    __syncthreads();
    const float s = s_scale;

    const uint2* __restrict__ src = reinterpret_cast<const uint2*>(g_scratch);
    float4* __restrict__ dst = reinterpret_cast<float4*>(out);

    for (int i = blockIdx.x * 256 + threadIdx.x; i < n4; i += gridDim.x * 256) {
        uint2 pk = src[i];
        __half2 h01 = *reinterpret_cast<__half2*>(&pk.x);
        __half2 h23 = *reinterpret_cast<__half2*>(&pk.y);
        float2 f01 = __half22float2(h01);
        float2 f23 = __half22float2(h23);
        float4 v;
        v.x = f01.x * s; v.y = f01.y * s;
        v.z = f23.x * s; v.w = f23.y * s;
        dst[i] = v;
    }
}

extern "C" void kernel_launch(void* const* d_in, const int* in_sizes, int n_in,
                              void* d_out, int out_size)
{
    const float* wave = (const float*)d_in[0];
    const float* wn   = (const float*)d_in[1];
    float* out = (float*)d_out;

    const int total  = in_sizes[0];
    const int T      = total / NCH;                       // 220500
    const int chunks = (T + U_ELEMS - 1) / U_ELEMS;       // 27
    const int nblk   = 32 * chunks;                       // 864; warps == NCH*chunks exactly

    pink_mix_kernel<<<nblk, WARPS_PB * 32>>>(wave, wn, T, chunks);

    const int n4 = total / 4;
    scale_expand_kernel<<<2048, 256>>>(out, n4, nblk);
}

// round 6
// speedup vs baseline: 1.2417x; 1.0862x over previous
#include <cuda_runtime.h>
#include <cuda_fp16.h>
#include <cstdint>

// EnvironmentalAugmentations: pink = IIR(white, a=0.99, b=0.01); mixed = wave + 0.05*pink;
// out = mixed / max(|mixed|) if max > 1 else mixed.
//
// R6 vs R5 (184.7us):
//  - pass1 widened to 8 elems/lane (256/warp-group): 2x float4 loads, one uint4
//    (16B) fp16 store, half the shuffle-scan work per element. Scratch rows padded
//    to TP (mult of 8) so STG.128 stays 16B-aligned on every channel.
//  - pass2 widened: uint4 (8 halfs) load + 2x float4 store per iter, block->(ch,part)
//    mapping keeps alignment under the padded stride.
//  - WARM 1024 -> 512 (0.99^512=5.9e-3 -> l2 contribution ~1e-6, under fp16 floor).
// Predicted 145-160us, rel_err ~2.1e-4.

#define A_COEF 0.99f
#define B_COEF 0.01f
#define NOISE_LEVEL 0.05f

constexpr int WARPS_PB = 8;          // warps per block (pass 1)
constexpr int U_ELEMS  = 8192;       // useful elements per warp tile
constexpr int WARM     = 512;        // warm-up elements (chunk > 0)
constexpr int GROUPS   = U_ELEMS / 256;
constexpr int WGROUPS  = WARM / 256;
constexpr int NCH      = 256;
constexpr int TP_MAX   = 221184;     // padded scratch row cap (27*8192)

__device__ __half g_scratch[(size_t)NCH * TP_MAX];  // fp16 mixed, padded rows
__device__ float  g_bmax[4096];                     // per-block maxima

__global__ __launch_bounds__(WARPS_PB * 32)
void pink_mix_kernel(const float* __restrict__ wave,
                     const float* __restrict__ wn,
                     int T, int chunks, int TP)
{
    const int lane   = threadIdx.x & 31;
    const int warpId = threadIdx.x >> 5;
    const int wgid   = blockIdx.x * WARPS_PB + warpId;
    const int ch     = wgid / chunks;
    const int chunk  = wgid - ch * chunks;

    const float A1 = A_COEF;
    const float A2 = A1 * A1;
    const float A3 = A2 * A1;
    const float A4 = A2 * A2;
    const float A5 = A4 * A1;
    const float A6 = A4 * A2;
    const float A7 = A4 * A3;
    const float A8 = A4 * A4;
    const float A16 = A8 * A8;
    const float A32 = A16 * A16;
    const float A64 = A32 * A32;
    const float A128 = A64 * A64;
    const float A256 = A128 * A128;
    const float a8lane = powf(A8, (float)lane);   // a^(8*lane)

    float lmax = 0.0f;

    if (ch < NCH) {
        const long long rowf = (long long)ch * T;
        const float* __restrict__ wnr = wn   + rowf;
        const float* __restrict__ wvr = wave + rowf;
        __half*      __restrict__ scr = g_scratch + (long long)ch * TP;

        const int ustart = chunk * U_ELEMS;
        const int nWarm  = (chunk == 0) ? 0 : WGROUPS;
        int tg = (chunk == 0) ? 0 : (ustart - WARM);

        float Cc = 0.0f;  // carry = pink value at element (tg-1)

        // ---- warm-up groups (256 elems each): scan only ----
        for (int g = 0; g < nWarm; ++g) {
            const int idx = tg + lane * 8;
            float4 wa = *reinterpret_cast<const float4*>(wnr + idx);
            float4 wb = *reinterpret_cast<const float4*>(wnr + idx + 4);
            float p0 = B_COEF * wa.x;
            float p1 = fmaf(A1, p0, B_COEF * wa.y);
            float p2 = fmaf(A1, p1, B_COEF * wa.z);
            float p3 = fmaf(A1, p2, B_COEF * wa.w);
            float p4 = fmaf(A1, p3, B_COEF * wb.x);
            float p5 = fmaf(A1, p4, B_COEF * wb.y);
            float p6 = fmaf(A1, p5, B_COEF * wb.z);
            float p7 = fmaf(A1, p6, B_COEF * wb.w);
            float tt = p7, u;
            u = __shfl_up_sync(0xffffffffu, tt, 1);  if (lane >= 1)  tt = fmaf(A8,   u, tt);
            u = __shfl_up_sync(0xffffffffu, tt, 2);  if (lane >= 2)  tt = fmaf(A16,  u, tt);
            u = __shfl_up_sync(0xffffffffu, tt, 4);  if (lane >= 4)  tt = fmaf(A32,  u, tt);
            u = __shfl_up_sync(0xffffffffu, tt, 8);  if (lane >= 8)  tt = fmaf(A64,  u, tt);
            u = __shfl_up_sync(0xffffffffu, tt, 16); if (lane >= 16) tt = fmaf(A128, u, tt);
            float T31 = __shfl_sync(0xffffffffu, tt, 31);
            Cc = fmaf(A256, Cc, T31);
            tg += 256;
        }

        // ---- useful groups: scan + mix + fp16 store + max ----
        for (int g = 0; g < GROUPS; ++g) {
            if (tg >= T) break;                      // warp-uniform
            const int idx = tg + lane * 8;
            const bool fullgrp = (tg + 256 <= T);

            float w0, w1, w2, w3, w4, w5, w6, w7;
            if (fullgrp) {
                float4 wa = *reinterpret_cast<const float4*>(wnr + idx);
                float4 wb = *reinterpret_cast<const float4*>(wnr + idx + 4);
                w0 = wa.x; w1 = wa.y; w2 = wa.z; w3 = wa.w;
                w4 = wb.x; w5 = wb.y; w6 = wb.z; w7 = wb.w;
            } else {
                w0 = (idx + 0 < T) ? wnr[idx + 0] : 0.0f;
                w1 = (idx + 1 < T) ? wnr[idx + 1] : 0.0f;
                w2 = (idx + 2 < T) ? wnr[idx + 2] : 0.0f;
                w3 = (idx + 3 < T) ? wnr[idx + 3] : 0.0f;
                w4 = (idx + 4 < T) ? wnr[idx + 4] : 0.0f;
                w5 = (idx + 5 < T) ? wnr[idx + 5] : 0.0f;
                w6 = (idx + 6 < T) ? wnr[idx + 6] : 0.0f;
                w7 = (idx + 7 < T) ? wnr[idx + 7] : 0.0f;
            }

            float g0 = B_COEF * w0;
            if (idx == 0) g0 = w0;                   // exact: pink[0] = w[0]
            float p0 = g0;
            float p1 = fmaf(A1, p0, B_COEF * w1);
            float p2 = fmaf(A1, p1, B_COEF * w2);
            float p3 = fmaf(A1, p2, B_COEF * w3);
            float p4 = fmaf(A1, p3, B_COEF * w4);
            float p5 = fmaf(A1, p4, B_COEF * w5);
            float p6 = fmaf(A1, p5, B_COEF * w6);
            float p7 = fmaf(A1, p6, B_COEF * w7);

            float tt = p7, u;
            u = __shfl_up_sync(0xffffffffu, tt, 1);  if (lane >= 1)  tt = fmaf(A8,   u, tt);
            u = __shfl_up_sync(0xffffffffu, tt, 2);  if (lane >= 2)  tt = fmaf(A16,  u, tt);
            u = __shfl_up_sync(0xffffffffu, tt, 4);  if (lane >= 4)  tt = fmaf(A32,  u, tt);
            u = __shfl_up_sync(0xffffffffu, tt, 8);  if (lane >= 8)  tt = fmaf(A64,  u, tt);
            u = __shfl_up_sync(0xffffffffu, tt, 16); if (lane >= 16) tt = fmaf(A128, u, tt);

            float Tm1 = __shfl_up_sync(0xffffffffu, tt, 1);
            float cin = fmaf(a8lane, Cc, (lane ? Tm1 : 0.0f));

            float f0 = fmaf(A1, cin, p0);
            float f1 = fmaf(A2, cin, p1);
            float f2 = fmaf(A3, cin, p2);
            float f3 = fmaf(A4, cin, p3);
            float f4 = fmaf(A5, cin, p4);
            float f5 = fmaf(A6, cin, p5);
            float f6 = fmaf(A7, cin, p6);
            float f7 = fmaf(A8, cin, p7);

            float T31 = __shfl_sync(0xffffffffu, tt, 31);
            Cc = fmaf(A256, Cc, T31);

            if (fullgrp) {
                float4 va = *reinterpret_cast<const float4*>(wvr + idx);
                float4 vb = *reinterpret_cast<const float4*>(wvr + idx + 4);
                float o0 = fmaf(NOISE_LEVEL, f0, va.x);
                float o1 = fmaf(NOISE_LEVEL, f1, va.y);
                float o2 = fmaf(NOISE_LEVEL, f2, va.z);
                float o3 = fmaf(NOISE_LEVEL, f3, va.w);
                float o4 = fmaf(NOISE_LEVEL, f4, vb.x);
                float o5 = fmaf(NOISE_LEVEL, f5, vb.y);
                float o6 = fmaf(NOISE_LEVEL, f6, vb.z);
                float o7 = fmaf(NOISE_LEVEL, f7, vb.w);
                __half2 h01 = __floats2half2_rn(o0, o1);
                __half2 h23 = __floats2half2_rn(o2, o3);
                __half2 h45 = __floats2half2_rn(o4, o5);
                __half2 h67 = __floats2half2_rn(o6, o7);
                uint4 pk;
                pk.x = *reinterpret_cast<unsigned*>(&h01);
                pk.y = *reinterpret_cast<unsigned*>(&h23);
                pk.z = *reinterpret_cast<unsigned*>(&h45);
                pk.w = *reinterpret_cast<unsigned*>(&h67);
                *reinterpret_cast<uint4*>(scr + idx) = pk;   // 16B aligned: TP%8==0, idx%8==0
                lmax = fmaxf(lmax, fmaxf(fmaxf(fabsf(o0), fabsf(o1)),
                                         fmaxf(fabsf(o2), fabsf(o3))));
                lmax = fmaxf(lmax, fmaxf(fmaxf(fabsf(o4), fabsf(o5)),
                                         fmaxf(fabsf(o6), fabsf(o7))));
            } else {
                float fs[8] = {f0, f1, f2, f3, f4, f5, f6, f7};
                float ws[8] = {0,0,0,0,0,0,0,0};
                ws[0]=w0; ws[1]=w1; ws[2]=w2; ws[3]=w3; ws[4]=w4; ws[5]=w5; ws[6]=w6; ws[7]=w7;
                #pragma unroll
                for (int j = 0; j < 8; ++j) {
                    if (idx + j < T) {
                        float oo = fmaf(NOISE_LEVEL, fs[j], wvr[idx + j]);
                        scr[idx + j] = __float2half_rn(oo);
                        lmax = fmaxf(lmax, fabsf(oo));
                    }
                }
                (void)ws;
            }
            tg += 256;
        }
    }

    // ---- block max reduction -> g_bmax[blockIdx.x] ----
    #pragma unroll
    for (int o = 16; o; o >>= 1)
        lmax = fmaxf(lmax, __shfl_xor_sync(0xffffffffu, lmax, o));

    __shared__ float smax[WARPS_PB];
    if (lane == 0) smax[warpId] = lmax;
    __syncthreads();
    if (warpId == 0) {
        float m = (lane < WARPS_PB) ? smax[lane] : 0.0f;
        #pragma unroll
        for (int o = 4; o; o >>= 1)
            m = fmaxf(m, __shfl_xor_sync(0xffffffffu, m, o));
        if (lane == 0) g_bmax[blockIdx.x] = m;
    }
}

// Pass 2: reduce per-block maxima; expand fp16 scratch (padded rows) -> scaled fp32 out.
// Grid = NCH*8 blocks: block b handles channel b>>3, part b&7 (span PS elems, PS%8==0).
__global__ __launch_bounds__(256)
void scale_expand_kernel(float* __restrict__ out, int T, int TP, int PS, int nb)
{
    // block-local reduction of g_bmax[0..nb)
    float m = 0.0f;
    for (int i = threadIdx.x; i < nb; i += 256)
        m = fmaxf(m, g_bmax[i]);
    #pragma unroll
    for (int o = 16; o; o >>= 1)
        m = fmaxf(m, __shfl_xor_sync(0xffffffffu, m, o));
    __shared__ float smax[8];
    if ((threadIdx.x & 31) == 0) smax[threadIdx.x >> 5] = m;
    __syncthreads();
    __shared__ float s_scale;
    if (threadIdx.x == 0) {
        float mm = smax[0];
        #pragma unroll
        for (int i = 1; i < 8; ++i) mm = fmaxf(mm, smax[i]);
        s_scale = (mm > 1.0f) ? (1.0f / mm) : 1.0f;
    }
    __syncthreads();
    const float s = s_scale;

    const int ch   = blockIdx.x >> 3;
    const int part = blockIdx.x & 7;
    const int start = part * PS;
    const int end   = min(start + PS, T);
    if (start >= T) return;

    const __half* __restrict__ src = g_scratch + (long long)ch * TP;
    float*        __restrict__ dst = out       + (long long)ch * T;

    // full 8-element groups, 16B load + 2x16B store per iter
    #pragma unroll 2
    for (int t = start + threadIdx.x * 8; t + 8 <= end; t += 256 * 8) {
        uint4 pk = *reinterpret_cast<const uint4*>(src + t);
        __half2 h01 = *reinterpret_cast<__half2*>(&pk.x);
        __half2 h23 = *reinterpret_cast<__half2*>(&pk.y);
        __half2 h45 = *reinterpret_cast<__half2*>(&pk.z);
        __half2 h67 = *reinterpret_cast<__half2*>(&pk.w);
        float2 f01 = __half22float2(h01);
        float2 f23 = __half22float2(h23);
        float2 f45 = __half22float2(h45);
        float2 f67 = __half22float2(h67);
        float4 va, vb;
        va.x = f01.x * s; va.y = f01.y * s; va.z = f23.x * s; va.w = f23.y * s;
        vb.x = f45.x * s; vb.y = f45.y * s; vb.z = f67.x * s; vb.w = f67.y * s;
        *reinterpret_cast<float4*>(dst + t)     = va;
        *reinterpret_cast<float4*>(dst + t + 4) = vb;
    }

    // tail (< 8 elems at region end)
    const int tfull = start + ((end - start) & ~7);
    const int rem   = end - tfull;
    if ((int)threadIdx.x < rem) {
        const int i = tfull + threadIdx.x;
        dst[i] = __half2float(src[i]) * s;
    }
}

extern "C" void kernel_launch(void* const* d_in, const int* in_sizes, int n_in,
                              void* d_out, int out_size)
{
    const float* wave = (const float*)d_in[0];
    const float* wn   = (const float*)d_in[1];
    float* out = (float*)d_out;

    const int total  = in_sizes[0];
    const int T      = total / NCH;                       // 220500
    const int chunks = (T + U_ELEMS - 1) / U_ELEMS;       // 27
    const int nblk   = (NCH * chunks) / WARPS_PB;         // 864 blocks (8 warps each)

    int TP = ((T + 127) / 128) * 128;                     // padded scratch row stride
    if (TP > TP_MAX) TP = TP_MAX;                         // (fits for T<=221184)
    const int PS = (((T + 7) / 8) + 7) & ~7;              // per-part span, mult of 8

    pink_mix_kernel<<<nblk, WARPS_PB * 32>>>(wave, wn, T, chunks, TP);
    scale_expand_kernel<<<NCH * 8, 256>>>(out, T, TP, PS, nblk);
}

// round 8
// speedup vs baseline: 1.3038x; 1.0500x over previous
#include <cuda_runtime.h>
#include <cuda_fp16.h>
#include <cstdint>

// EnvironmentalAugmentations: pink = IIR(white, a=0.99, b=0.01); mixed = wave + 0.05*pink;
// out = mixed / max(|mixed|) if max > 1 else mixed.
//
// R8 = resubmission of R7 (broker-level container flake; identical sources have
// always passed on retry). vs R6 (170.0us):
//  - pass2 coalescing fixed (R6's 8-half/thread made every STG.128 write half-sectors
//    at 32B stride -> L1 wavefronts doubled, DRAM% fell to 51%). Back to 4 floats/thread
//    (uint2 load + float4 store, warp-contiguous) with ILP=4 independent slots.
//  - L2-residency: scratch (113MB) nearly fits L2 (126MB). Pass1 streaming reads use
//    __ldcs (evict-first) and pass2 out-stores use __stcs so scratch stays resident;
//    pass2's scratch read then mostly hits L2 (~113MB DRAM read saved).
// Predicted 142-152us, rel_err ~2.1e-4.

#define A_COEF 0.99f
#define B_COEF 0.01f
#define NOISE_LEVEL 0.05f

constexpr int WARPS_PB = 8;          // warps per block (pass 1)
constexpr int U_ELEMS  = 8192;       // useful elements per warp tile
constexpr int WARM     = 512;        // warm-up elements (chunk > 0): 0.99^512=5.9e-3
constexpr int GROUPS   = U_ELEMS / 256;
constexpr int WGROUPS  = WARM / 256;
constexpr int NCH      = 256;
constexpr int TP_MAX   = 221184;     // padded scratch row cap

__device__ __half g_scratch[(size_t)NCH * TP_MAX];  // fp16 mixed, padded rows
__device__ float  g_bmax[4096];                     // per-block maxima

__global__ __launch_bounds__(WARPS_PB * 32)
void pink_mix_kernel(const float* __restrict__ wave,
                     const float* __restrict__ wn,
                     int T, int chunks, int TP)
{
    const int lane   = threadIdx.x & 31;
    const int warpId = threadIdx.x >> 5;
    const int wgid   = blockIdx.x * WARPS_PB + warpId;
    const int ch     = wgid / chunks;
    const int chunk  = wgid - ch * chunks;

    const float A1 = A_COEF;
    const float A2 = A1 * A1;
    const float A3 = A2 * A1;
    const float A4 = A2 * A2;
    const float A5 = A4 * A1;
    const float A6 = A4 * A2;
    const float A7 = A4 * A3;
    const float A8 = A4 * A4;
    const float A16 = A8 * A8;
    const float A32 = A16 * A16;
    const float A64 = A32 * A32;
    const float A128 = A64 * A64;
    const float A256 = A128 * A128;
    const float a8lane = powf(A8, (float)lane);   // a^(8*lane)

    float lmax = 0.0f;

    if (ch < NCH) {
        const long long rowf = (long long)ch * T;
        const float* __restrict__ wnr = wn   + rowf;
        const float* __restrict__ wvr = wave + rowf;
        __half*      __restrict__ scr = g_scratch + (long long)ch * TP;

        const int ustart = chunk * U_ELEMS;
        const int nWarm  = (chunk == 0) ? 0 : WGROUPS;
        int tg = (chunk == 0) ? 0 : (ustart - WARM);

        float Cc = 0.0f;  // carry = pink value at element (tg-1)

        // ---- warm-up groups (256 elems each): scan only ----
        for (int g = 0; g < nWarm; ++g) {
            const int idx = tg + lane * 8;
            float4 wa = __ldcs(reinterpret_cast<const float4*>(wnr + idx));
            float4 wb = __ldcs(reinterpret_cast<const float4*>(wnr + idx + 4));
            float p0 = B_COEF * wa.x;
            float p1 = fmaf(A1, p0, B_COEF * wa.y);
            float p2 = fmaf(A1, p1, B_COEF * wa.z);
            float p3 = fmaf(A1, p2, B_COEF * wa.w);
            float p4 = fmaf(A1, p3, B_COEF * wb.x);
            float p5 = fmaf(A1, p4, B_COEF * wb.y);
            float p6 = fmaf(A1, p5, B_COEF * wb.z);
            float p7 = fmaf(A1, p6, B_COEF * wb.w);
            float tt = p7, u;
            u = __shfl_up_sync(0xffffffffu, tt, 1);  if (lane >= 1)  tt = fmaf(A8,   u, tt);
            u = __shfl_up_sync(0xffffffffu, tt, 2);  if (lane >= 2)  tt = fmaf(A16,  u, tt);
            u = __shfl_up_sync(0xffffffffu, tt, 4);  if (lane >= 4)  tt = fmaf(A32,  u, tt);
            u = __shfl_up_sync(0xffffffffu, tt, 8);  if (lane >= 8)  tt = fmaf(A64,  u, tt);
            u = __shfl_up_sync(0xffffffffu, tt, 16); if (lane >= 16) tt = fmaf(A128, u, tt);
            float T31 = __shfl_sync(0xffffffffu, tt, 31);
            Cc = fmaf(A256, Cc, T31);
            tg += 256;
        }

        // ---- useful groups: scan + mix + fp16 store + max ----
        for (int g = 0; g < GROUPS; ++g) {
            if (tg >= T) break;                      // warp-uniform
            const int idx = tg + lane * 8;
            const bool fullgrp = (tg + 256 <= T);

            float w0, w1, w2, w3, w4, w5, w6, w7;
            if (fullgrp) {
                float4 wa = __ldcs(reinterpret_cast<const float4*>(wnr + idx));
                float4 wb = __ldcs(reinterpret_cast<const float4*>(wnr + idx + 4));
                w0 = wa.x; w1 = wa.y; w2 = wa.z; w3 = wa.w;
                w4 = wb.x; w5 = wb.y; w6 = wb.z; w7 = wb.w;
            } else {
                w0 = (idx + 0 < T) ? wnr[idx + 0] : 0.0f;
                w1 = (idx + 1 < T) ? wnr[idx + 1] : 0.0f;
                w2 = (idx + 2 < T) ? wnr[idx + 2] : 0.0f;
                w3 = (idx + 3 < T) ? wnr[idx + 3] : 0.0f;
                w4 = (idx + 4 < T) ? wnr[idx + 4] : 0.0f;
                w5 = (idx + 5 < T) ? wnr[idx + 5] : 0.0f;
                w6 = (idx + 6 < T) ? wnr[idx + 6] : 0.0f;
                w7 = (idx + 7 < T) ? wnr[idx + 7] : 0.0f;
            }

            float g0 = B_COEF * w0;
            if (idx == 0) g0 = w0;                   // exact: pink[0] = w[0]
            float p0 = g0;
            float p1 = fmaf(A1, p0, B_COEF * w1);
            float p2 = fmaf(A1, p1, B_COEF * w2);
            float p3 = fmaf(A1, p2, B_COEF * w3);
            float p4 = fmaf(A1, p3, B_COEF * w4);
            float p5 = fmaf(A1, p4, B_COEF * w5);
            float p6 = fmaf(A1, p5, B_COEF * w6);
            float p7 = fmaf(A1, p6, B_COEF * w7);

            float tt = p7, u;
            u = __shfl_up_sync(0xffffffffu, tt, 1);  if (lane >= 1)  tt = fmaf(A8,   u, tt);
            u = __shfl_up_sync(0xffffffffu, tt, 2);  if (lane >= 2)  tt = fmaf(A16,  u, tt);
            u = __shfl_up_sync(0xffffffffu, tt, 4);  if (lane >= 4)  tt = fmaf(A32,  u, tt);
            u = __shfl_up_sync(0xffffffffu, tt, 8);  if (lane >= 8)  tt = fmaf(A64,  u, tt);
            u = __shfl_up_sync(0xffffffffu, tt, 16); if (lane >= 16) tt = fmaf(A128, u, tt);

            float Tm1 = __shfl_up_sync(0xffffffffu, tt, 1);
            float cin = fmaf(a8lane, Cc, (lane ? Tm1 : 0.0f));

            float f0 = fmaf(A1, cin, p0);
            float f1 = fmaf(A2, cin, p1);
            float f2 = fmaf(A3, cin, p2);
            float f3 = fmaf(A4, cin, p3);
            float f4 = fmaf(A5, cin, p4);
            float f5 = fmaf(A6, cin, p5);
            float f6 = fmaf(A7, cin, p6);
            float f7 = fmaf(A8, cin, p7);

            float T31 = __shfl_sync(0xffffffffu, tt, 31);
            Cc = fmaf(A256, Cc, T31);

            if (fullgrp) {
                float4 va = __ldcs(reinterpret_cast<const float4*>(wvr + idx));
                float4 vb = __ldcs(reinterpret_cast<const float4*>(wvr + idx + 4));
                float o0 = fmaf(NOISE_LEVEL, f0, va.x);
                float o1 = fmaf(NOISE_LEVEL, f1, va.y);
                float o2 = fmaf(NOISE_LEVEL, f2, va.z);
                float o3 = fmaf(NOISE_LEVEL, f3, va.w);
                float o4 = fmaf(NOISE_LEVEL, f4, vb.x);
                float o5 = fmaf(NOISE_LEVEL, f5, vb.y);
                float o6 = fmaf(NOISE_LEVEL, f6, vb.z);
                float o7 = fmaf(NOISE_LEVEL, f7, vb.w);
                __half2 h01 = __floats2half2_rn(o0, o1);
                __half2 h23 = __floats2half2_rn(o2, o3);
                __half2 h45 = __floats2half2_rn(o4, o5);
                __half2 h67 = __floats2half2_rn(o6, o7);
                uint4 pk;
                pk.x = *reinterpret_cast<unsigned*>(&h01);
                pk.y = *reinterpret_cast<unsigned*>(&h23);
                pk.z = *reinterpret_cast<unsigned*>(&h45);
                pk.w = *reinterpret_cast<unsigned*>(&h67);
                *reinterpret_cast<uint4*>(scr + idx) = pk;   // default policy: stay in L2
                lmax = fmaxf(lmax, fmaxf(fmaxf(fabsf(o0), fabsf(o1)),
                                         fmaxf(fabsf(o2), fabsf(o3))));
                lmax = fmaxf(lmax, fmaxf(fmaxf(fabsf(o4), fabsf(o5)),
                                         fmaxf(fabsf(o6), fabsf(o7))));
            } else {
                float fs[8] = {f0, f1, f2, f3, f4, f5, f6, f7};
                #pragma unroll
                for (int j = 0; j < 8; ++j) {
                    if (idx + j < T) {
                        float oo = fmaf(NOISE_LEVEL, fs[j], wvr[idx + j]);
                        scr[idx + j] = __float2half_rn(oo);
                        lmax = fmaxf(lmax, fabsf(oo));
                    }
                }
            }
            tg += 256;
        }
    }

    // ---- block max reduction -> g_bmax[blockIdx.x] ----
    #pragma unroll
    for (int o = 16; o; o >>= 1)
        lmax = fmaxf(lmax, __shfl_xor_sync(0xffffffffu, lmax, o));

    __shared__ float smax[WARPS_PB];
    if (lane == 0) smax[warpId] = lmax;
    __syncthreads();
    if (warpId == 0) {
        float m = (lane < WARPS_PB) ? smax[lane] : 0.0f;
        #pragma unroll
        for (int o = 4; o; o >>= 1)
            m = fmaxf(m, __shfl_xor_sync(0xffffffffu, m, o));
        if (lane == 0) g_bmax[blockIdx.x] = m;
    }
}

// Pass 2: reduce per-block maxima; expand fp16 scratch (padded rows) -> scaled fp32 out.
// Grid = NCH*8 blocks: block b handles channel b>>3, part b&7. Thread granularity:
// 4 floats (uint2 load + float4 store, warp-contiguous), ILP=4 independent slots.
__global__ __launch_bounds__(256)
void scale_expand_kernel(float* __restrict__ out, int T, int TP, int PS, int nb)
{
    float m = 0.0f;
    for (int i = threadIdx.x; i < nb; i += 256)
        m = fmaxf(m, g_bmax[i]);
    #pragma unroll
    for (int o = 16; o; o >>= 1)
        m = fmaxf(m, __shfl_xor_sync(0xffffffffu, m, o));
    __shared__ float smax[8];
    if ((threadIdx.x & 31) == 0) smax[threadIdx.x >> 5] = m;
    __syncthreads();
    __shared__ float s_scale;
    if (threadIdx.x == 0) {
        float mm = smax[0];
        #pragma unroll
        for (int i = 1; i < 8; ++i) mm = fmaxf(mm, smax[i]);
        s_scale = (mm > 1.0f) ? (1.0f / mm) : 1.0f;
    }
    __syncthreads();
    const float s = s_scale;

    const int ch   = blockIdx.x >> 3;
    const int part = blockIdx.x & 7;
    const int start = part * PS;                 // PS mult of 8 -> 16B-aligned base
    const int end   = min(start + PS, T);
    if (start >= T) return;

    const __half* __restrict__ src = g_scratch + (long long)ch * TP;
    float*        __restrict__ dst = out       + (long long)ch * T;

    constexpr int STEP = 256 * 4;                // elems per slot (1024)

    auto do4 = [&](int t) {
        uint2 pk = __ldcs(reinterpret_cast<const uint2*>(src + t));
        __half2 h01 = *reinterpret_cast<__half2*>(&pk.x);
        __half2 h23 = *reinterpret_cast<__half2*>(&pk.y);
        float2 f01 = __half22float2(h01);
        float2 f23 = __half22float2(h23);
        float4 v;
        v.x = f01.x * s; v.y = f01.y * s; v.z = f23.x * s; v.w = f23.y * s;
        __stcs(reinterpret_cast<float4*>(dst + t), v);
    };

    int t = start + threadIdx.x * 4;
    // ILP=4 main loop: 4 independent slots per iteration
    for (; t + 3 * STEP + 4 <= end; t += 4 * STEP) {
        do4(t);
        do4(t + STEP);
        do4(t + 2 * STEP);
        do4(t + 3 * STEP);
    }
    // remainder slots
    for (; t + 4 <= end; t += STEP)
        do4(t);
    // scalar tail (< 4 elems at region end)
    {
        const int tfull = start + ((end - start) & ~3);
        const int rem   = end - tfull;
        if ((int)threadIdx.x < rem) {
            const int i = tfull + threadIdx.x;
            dst[i] = __half2float(src[i]) * s;
        }
    }
}

extern "C" void kernel_launch(void* const* d_in, const int* in_sizes, int n_in,
                              void* d_out, int out_size)
{
    const float* wave = (const float*)d_in[0];
    const float* wn   = (const float*)d_in[1];
    float* out = (float*)d_out;

    const int total  = in_sizes[0];
    const int T      = total / NCH;                       // 220500
    const int chunks = (T + U_ELEMS - 1) / U_ELEMS;       // 27
    const int nblk   = (NCH * chunks) / WARPS_PB;         // 864 blocks

    int TP = ((T + 127) / 128) * 128;                     // padded scratch row stride
    if (TP > TP_MAX) TP = TP_MAX;
    const int PS = (((T + 7) / 8) + 7) & ~7;              // per-part span, mult of 8

    pink_mix_kernel<<<nblk, WARPS_PB * 32>>>(wave, wn, T, chunks, TP);
    scale_expand_kernel<<<NCH * 8, 256>>>(out, T, TP, PS, nblk);
}